// round 2
// baseline (speedup 1.0000x reference)
#include <cuda_runtime.h>

// CheapTrick liftering: out = irfft( (rfft(log(even_ext(x))).real) * sm[f0] * cp[f0] )[:1025]
// pack -> FFT1024 (radix-4 DIF) -> fused untangle+lifter+re-tangle (scrambled domain)
// -> IFFT1024 (radix-4 DIT) -> unpack.  One CTA per frame.
// All shared-memory z[] accesses go through an XOR bank swizzle (bijective on 0..1023)
// that makes every FFT pass conflict-free per half-warp.

#define BIN   1025
#define NFFT  1024
#define NTH   256

// bank swizzle: bijection on [0,1024); XOR of high bits into low 4 (bank-pair) bits
__device__ __forceinline__ int SW(int i) {
    return i ^ ((i >> 4) & 15) ^ ((i >> 2) & 12);
}

__device__ __forceinline__ int rev4_10(int x) {
    // reverse five base-4 digits of a 10-bit index
    return ((x & 3) << 8) | (((x >> 2) & 3) << 6) | (((x >> 4) & 3) << 4)
         | (((x >> 6) & 3) << 2) | ((x >> 8) & 3);
}

__global__ __launch_bounds__(NTH) void cheaptrick_kernel(
    const float* __restrict__ x,
    const int*   __restrict__ f0,
    const float* __restrict__ sml,
    const float* __restrict__ cpl,
    float*       __restrict__ out)
{
    __shared__ float2 z[NFFT];     // complex work buffer (swizzled addressing)
    __shared__ float2 tw[768];     // tw[j] = exp(-2*pi*i*j/1024)

    const int tid   = threadIdx.x;
    const int frame = blockIdx.x;
    const float* xr   = x   + (size_t)frame * BIN;
    float*       orow = out + (size_t)frame * BIN;
    const int f = f0[frame];
    const float* smr = sml + (size_t)f * BIN;
    const float* cpr = cpl + (size_t)f * BIN;

    // ---- twiddle table ----
    for (int j = tid; j < 768; j += NTH) {
        float s, c;
        __sincosf(-6.28318530717958647692f * (float)j * (1.0f / 1024.0f), &s, &c);
        tw[j] = make_float2(c, s);
    }

    // ---- pack: y = even extension of L = log(x); z[m] = y[2m] + i*y[2m+1] ----
    for (int n = tid; n < BIN; n += NTH) {
        float Lv = __logf(xr[n]);
        int h = n >> 1;
        if ((n & 1) == 0) {
            z[SW(h)].x = Lv;                                   // m = n/2
            if (n >= 2 && n <= 1022) z[SW(1024 - h)].x = Lv;   // mirror
        } else {
            z[SW(h)].y = Lv;                                   // m = (n-1)/2
            z[SW(1023 - h)].y = Lv;                            // mirror
        }
    }
    __syncthreads();

    // ---- forward FFT1024, radix-4 DIF (natural in -> digit-reversed out) ----
    #pragma unroll
    for (int p = 0; p < 5; p++) {
        const int L = 256 >> (2 * p);
        const int S = 1 << (2 * p);
        const int j    = tid & (L - 1);
        const int blk  = tid >> (8 - 2 * p);
        const int base = blk * (L << 2) + j;
        const int iA = SW(base), iB = SW(base + L), iC = SW(base + 2 * L), iD = SW(base + 3 * L);
        float2 a = z[iA], b = z[iB], c = z[iC], d = z[iD];
        float t0r = a.x + c.x, t0i = a.y + c.y;
        float t1r = a.x - c.x, t1i = a.y - c.y;
        float t2r = b.x + d.x, t2i = b.y + d.y;
        float t3r = b.x - d.x, t3i = b.y - d.y;
        float r0r = t0r + t2r, r0i = t0i + t2i;
        float r2r = t0r - t2r, r2i = t0i - t2i;
        float r1r = t1r + t3i, r1i = t1i - t3r;   // t1 - i*t3
        float r3r = t1r - t3i, r3i = t1i + t3r;   // t1 + i*t3
        const int i1 = j * S;
        float2 w1 = tw[i1], w2 = tw[2 * i1], w3 = tw[3 * i1];
        z[iA] = make_float2(r0r, r0i);
        z[iB] = make_float2(r1r * w1.x - r1i * w1.y, r1r * w1.y + r1i * w1.x);
        z[iC] = make_float2(r2r * w2.x - r2i * w2.y, r2r * w2.y + r2i * w2.x);
        z[iD] = make_float2(r3r * w3.x - r3i * w3.y, r3r * w3.y + r3i * w3.x);
        __syncthreads();
    }

    // ---- fused: untangle rfft2048 -> cepstrum.real -> lifter -> re-tangle for irfft ----
    const float inv1024 = 1.0f / 1024.0f;
    for (int k = tid; k <= 512; k += NTH) {
        if (k == 0) {
            float2 Z0 = z[SW(0)];
            float cep0 = Z0.x + Z0.y;           // Re Y[0]
            float cepN = Z0.x - Z0.y;           // Re Y[1024]
            float S0 = cep0 * smr[0]    * cpr[0]    * inv1024;
            float SN = cepN * smr[1024] * cpr[1024] * inv1024;
            z[SW(0)] = make_float2(0.5f * (S0 + SN), 0.5f * (S0 - SN));
        } else if (k == 512) {
            const int p2 = SW(2);               // rev4(512) = 2
            float2 Zm = z[p2];
            float Sm = Zm.x * smr[512] * cpr[512] * inv1024;
            z[p2] = make_float2(Sm, 0.0f);
        } else {
            const int pA = SW(rev4_10(k));
            const int pB = SW(rev4_10(1024 - k));
            float2 Za = z[pA], Zb = z[pB];
            float s, c;
            __sincosf(3.14159265358979323846f * (float)k * (1.0f / 1024.0f), &s, &c);
            float sumr = Za.x + Zb.x;
            float sumi = Za.y + Zb.y;
            float difr = Za.x - Zb.x;
            float cepA = 0.5f * (sumr + c * sumi - s * difr);   // Re Y[k]
            float cepB = 0.5f * (sumr - c * sumi + s * difr);   // Re Y[1024-k]
            float SA = cepA * smr[k]        * cpr[k]        * inv1024;
            float SB = cepB * smr[1024 - k] * cpr[1024 - k] * inv1024;
            float mm = 0.5f * (SA + SB);
            float dd = 0.5f * (SA - SB);
            z[pA] = make_float2(mm - dd * s, dd * c);
            z[pB] = make_float2(mm + dd * s, dd * c);
        }
    }
    __syncthreads();

    // ---- inverse FFT1024, radix-4 DIT (digit-reversed in -> natural out), conj twiddles ----
    #pragma unroll
    for (int p = 0; p < 5; p++) {
        const int L = 1 << (2 * p);
        const int S = 256 >> (2 * p);
        const int j    = tid & (L - 1);
        const int blk  = tid >> (2 * p);
        const int base = blk * (L << 2) + j;
        const int iA = SW(base), iB = SW(base + L), iC = SW(base + 2 * L), iD = SW(base + 3 * L);
        float2 a  = z[iA];
        float2 b0 = z[iB], c0 = z[iC], d0 = z[iD];
        const int i1 = j * S;
        float2 w1 = tw[i1], w2 = tw[2 * i1], w3 = tw[3 * i1];
        // multiply by conj(w)
        float br = b0.x * w1.x + b0.y * w1.y, bi = b0.y * w1.x - b0.x * w1.y;
        float cr = c0.x * w2.x + c0.y * w2.y, ci = c0.y * w2.x - c0.x * w2.y;
        float dr = d0.x * w3.x + d0.y * w3.y, di = d0.y * w3.x - d0.x * w3.y;
        float t0r = a.x + cr, t0i = a.y + ci;
        float t1r = a.x - cr, t1i = a.y - ci;
        float t2r = br + dr,  t2i = bi + di;
        float t3r = br - dr,  t3i = bi - di;
        z[iA] = make_float2(t0r + t2r, t0i + t2i);
        z[iB] = make_float2(t1r - t3i, t1i + t3r);   // t1 + i*t3
        z[iC] = make_float2(t0r - t2r, t0i - t2i);
        z[iD] = make_float2(t1r + t3i, t1i - t3r);   // t1 - i*t3
        __syncthreads();
    }

    // ---- unpack: out[n] = y[n], n = 0..1024 ----
    for (int n = tid; n < BIN; n += NTH) {
        float2 v = z[SW(n >> 1)];
        orow[n] = (n & 1) ? v.y : v.x;
    }
}

extern "C" void kernel_launch(void* const* d_in, const int* in_sizes, int n_in,
                              void* d_out, int out_size) {
    const float* x  = (const float*)d_in[0];
    const int*   f0 = (const int*)d_in[1];
    const float* sm = (const float*)d_in[2];
    const float* cp = (const float*)d_in[3];
    float* out = (float*)d_out;
    const int frames = in_sizes[1];   // B*T
    cheaptrick_kernel<<<frames, NTH>>>(x, f0, sm, cp, out);
}